// round 14
// baseline (speedup 1.0000x reference)
#include <cuda_runtime.h>
#include <cuda_fp16.h>
#include <math.h>
#include <float.h>

#define B   8
#define F   2048
#define NN  10000
#define J   10
#define R   20
#define H1  200
#define H2  100

#define FS   16           // F splits
#define FC   (F/FS)       // 128 f-rows per block
#define TPB1 128
#define WINF 512          // floats per n-window (2KB transfers — do not shrink; R10)
#define NBLK1 ((NN + WINF - 1)/WINF)   // 20
#define NST  4            // pipeline stages
#define CROWS 2           // f-rows per stage/chunk (4KB stages)
#define NCHUNK (FC/CROWS) // 64

#define WS_BYTES    (FC*J*8)          // float2 dup weights: 10240
#define STAGE_BYTES (CROWS*WINF*4)    // 4096 per stage
#define SMEM_CONV   (WS_BYTES + NST*STAGE_BYTES + 64)   // ~26.7KB -> 6 CTAs/SM
// conv grid = 20*16*8 = 2560 over 148*6=888 capacity = 2.88 waves (96% avg residency)

// Scratch (device globals: no allocation allowed)
__device__ __align__(16) __half g_parth[(size_t)FS*B*J*NN];  // 25.6 MB fp16 partials
__device__ float g_mmh[B*J*2*2*20];   // per-(bj,half): top20 desc, bot20 asc
__device__ unsigned g_done;           // select-block completion counter

#define FMA2(acc, w, xv) asm("fma.rn.f32x2 %0, %1, %2, %0;" : "+l"(acc) : "l"(w), "l"(xv))

__device__ __forceinline__ unsigned smem_u32(const void* p) {
    return (unsigned)__cvta_generic_to_shared(p);
}
__device__ __forceinline__ void mbar_init(unsigned mbar, unsigned cnt) {
    asm volatile("mbarrier.init.shared::cta.b64 [%0], %1;" :: "r"(mbar), "r"(cnt) : "memory");
}
__device__ __forceinline__ void mbar_expect_tx(unsigned mbar, unsigned bytes) {
    asm volatile("mbarrier.arrive.expect_tx.shared::cta.b64 _, [%0], %1;" :: "r"(mbar), "r"(bytes) : "memory");
}
__device__ __forceinline__ void mbar_wait(unsigned mbar, unsigned phase) {
    asm volatile(
        "{\n\t.reg .pred P;\n\t"
        "W_%=:\n\t"
        "mbarrier.try_wait.parity.shared::cta.b64 P, [%0], %1, 0x989680;\n\t"
        "@!P bra W_%=;\n\t}"
        :: "r"(mbar), "r"(phase) : "memory");
}
__device__ __forceinline__ void bulk_g2s(unsigned dst, const void* src, unsigned bytes, unsigned mbar) {
    asm volatile(
        "cp.async.bulk.shared::cta.global.mbarrier::complete_tx::bytes [%0], [%1], %2, [%3];"
        :: "r"(dst), "l"(src), "r"(bytes), "r"(mbar) : "memory");
}

// ---------------------------------------------------------------------------
// Kernel 1: 1x1 conv partials via cp.async.bulk staging (unchanged R12 WIN).
// g_parth[fs][b][j][n] = (half) sum_{f in chunk} x[b,f,n]*w[j,f]
// ---------------------------------------------------------------------------
__global__ __launch_bounds__(TPB1, 6)
void conv_kernel(const float* __restrict__ x, const float* __restrict__ cw)
{
    extern __shared__ __align__(16) unsigned char smem_raw[];
    float2* ws     = (float2*)smem_raw;                          // [FC][J] dup pairs
    float*  stages = (float*)(smem_raw + WS_BYTES);              // [NST][CROWS][WINF]
    unsigned mbar0 = smem_u32(smem_raw + WS_BYTES + NST*STAGE_BYTES);

    const int b   = blockIdx.z;
    const int fs  = blockIdx.y;
    const int f0  = fs * FC;
    const int n0  = blockIdx.x * WINF;
    const int wfl = (NN - n0 < WINF) ? (NN - n0) : WINF;
    const unsigned wbytes = (unsigned)wfl * 4u;
    const int tid = threadIdx.x;

    for (int i = tid; i < FC*J; i += TPB1) {
        int f = i / J, j = i - f*J;
        float w = cw[j*F + f0 + f];
        ws[i] = make_float2(w, w);
    }
    if (tid == 0) {
        #pragma unroll
        for (int s = 0; s < NST; s++) mbar_init(mbar0 + 8*s, 1);
    }
    __syncthreads();

    const float* xbase = x + ((size_t)b*F + f0)*NN + n0;

    if (tid == 0) {
        #pragma unroll
        for (int s = 0; s < NST; s++) {
            mbar_expect_tx(mbar0 + 8*s, wbytes * CROWS);
            unsigned dst = smem_u32(stages + s*CROWS*WINF);
            const float* src = xbase + (size_t)(s*CROWS)*NN;
            #pragma unroll
            for (int u = 0; u < CROWS; u++)
                bulk_g2s(dst + u*WINF*4, src + (size_t)u*NN, wbytes, mbar0 + 8*s);
        }
    }

    unsigned long long acc0[J], acc1[J];
    #pragma unroll
    for (int j = 0; j < J; j++) { acc0[j] = 0ull; acc1[j] = 0ull; }

    const int col = 4*tid;

    #pragma unroll 1
    for (int c = 0; c < NCHUNK; c++) {
        const int slot = c & (NST-1);
        mbar_wait(mbar0 + 8*slot, (c >> 2) & 1);

        const float* st = stages + slot*CROWS*WINF + col;
        #pragma unroll
        for (int u = 0; u < CROWS; u++) {
            ulonglong2 xv = *(const ulonglong2*)(st + u*WINF);
            const ulonglong2* wp = (const ulonglong2*)&ws[(c*CROWS + u)*J];
            #pragma unroll
            for (int jj = 0; jj < 5; jj++) {
                ulonglong2 w2 = wp[jj];
                FMA2(acc0[2*jj  ], w2.x, xv.x);
                FMA2(acc1[2*jj  ], w2.x, xv.y);
                FMA2(acc0[2*jj+1], w2.y, xv.x);
                FMA2(acc1[2*jj+1], w2.y, xv.y);
            }
        }
        __syncthreads();
        if (tid == 0 && c + NST < NCHUNK) {
            int nc = c + NST;
            mbar_expect_tx(mbar0 + 8*slot, wbytes * CROWS);
            unsigned dst = smem_u32(stages + slot*CROWS*WINF);
            const float* src = xbase + (size_t)(nc*CROWS)*NN;
            #pragma unroll
            for (int u = 0; u < CROWS; u++)
                bulk_g2s(dst + u*WINF*4, src + (size_t)u*NN, wbytes, mbar0 + 8*slot);
        }
    }

    if (col < wfl) {
        __half* outp = g_parth + (((size_t)fs*B + b)*J)*NN + n0 + col;
        #pragma unroll
        for (int j = 0; j < J; j++) {
            float a, bb, cc, d;
            asm("mov.b64 {%0,%1}, %2;" : "=f"(a), "=f"(bb) : "l"(acc0[j]));
            asm("mov.b64 {%0,%1}, %2;" : "=f"(cc), "=f"(d) : "l"(acc1[j]));
            __half2 h0 = __floats2half2_rn(a, bb);
            __half2 h1 = __floats2half2_rn(cc, d);
            uint2 u2;
            u2.x = reinterpret_cast<unsigned&>(h0);
            u2.y = reinterpret_cast<unsigned&>(h1);
            *(uint2*)(outp + (size_t)j*NN) = u2;
        }
    }
}

// ---------------------------------------------------------------------------
// Kernel 2 (fused): R12's proven shfl-based select (NO REDUX — R13 showed
// REDUX serializes on the atomic unit, +29us), plus last-block MLP tail.
// ---------------------------------------------------------------------------
#define TPB2 1024
#define GROUPS (NN/4)         // 2500
#define HGRP (GROUPS/2)       // 1250 per half
#define LSTRIDE 10            // sentinel + 8 vals + tail sentinel
#define NSEL (B*J*2)          // 160 blocks
#define SMEM_SEL 49152        // union: select phase 46.3KB / mlp phase 48KB

__global__ __launch_bounds__(TPB2)
void select_kernel(const float* __restrict__ cb,
                   const float* __restrict__ w1, const float* __restrict__ b1,
                   const float* __restrict__ w2, const float* __restrict__ b2,
                   const float* __restrict__ w3, const float* __restrict__ b3,
                   float* __restrict__ out)
{
    extern __shared__ __align__(16) unsigned char sbuf[];
    // --- select-phase layout ---
    float* s = (float*)sbuf;                                 // [TPB2][LSTRIDE] 40960B
    float (*wt)[21] = (float(*)[21])(sbuf + 40960);          // 2688B
    float (*wb)[21] = (float(*)[21])(sbuf + 40960 + 2688);   // 2688B
    __shared__ int is_last;

    const int bid = blockIdx.x;
    const int half = bid & 1, bj = bid >> 1;
    const int b = bj / J, j = bj - b*J;
    const int tid = threadIdx.x;
    const int lane = tid & 31, wid = tid >> 5;
    const unsigned FULL = 0xffffffffu;

    // Warm L2 with the MLP weights.
    {
        int gid = bid * TPB2 + tid;
        if (gid < (2*R*J)*H1/32) {
            asm volatile("prefetch.global.L2 [%0];" :: "l"(w1 + gid*32));
        } else if (gid < (2*R*J)*H1/32 + H1*H2/32) {
            asm volatile("prefetch.global.L2 [%0];" :: "l"(w2 + (gid - (2*R*J)*H1/32)*32));
        } else if (gid < (2*R*J)*H1/32 + H1*H2/32 + 7) {
            asm volatile("prefetch.global.L2 [%0];" :: "l"(w3 + (gid - (2*R*J)*H1/32 - H1*H2/32)*32));
        }
    }

    float v[8];
    #pragma unroll
    for (int k = 0; k < 8; k++) v[k] = -FLT_MAX;
    int c = 0;
    #pragma unroll
    for (int k = 0; k < 2; k++) {
        int l = tid + k*TPB2;
        if (l < HGRP) {
            int gidx = half*HGRP + l;
            float4 acc = make_float4(0.f, 0.f, 0.f, 0.f);
            #pragma unroll
            for (int fs = 0; fs < FS; fs++) {
                const uint2* p = (const uint2*)(g_parth + (((size_t)fs*B + b)*J + j)*NN);
                uint2 raw = p[gidx];
                __half2 h0 = reinterpret_cast<__half2&>(raw.x);
                __half2 h1 = reinterpret_cast<__half2&>(raw.y);
                float2 f0 = __half22float2(h0);
                float2 f1 = __half22float2(h1);
                acc.x += f0.x; acc.y += f0.y; acc.z += f1.x; acc.w += f1.y;
            }
            v[4*k+0] = acc.x; v[4*k+1] = acc.y; v[4*k+2] = acc.z; v[4*k+3] = acc.w;
            c += 4;
        }
    }

    // Odd-even transposition sort, descending (8 passes).
    #pragma unroll
    for (int pass = 0; pass < 8; pass++) {
        #pragma unroll
        for (int i = (pass & 1); i + 1 < 8; i += 2) {
            float hi = fmaxf(v[i], v[i+1]);
            float lo = fminf(v[i], v[i+1]);
            v[i] = hi; v[i+1] = lo;
        }
    }

    float* my = s + tid*LSTRIDE;
    my[0] = FLT_MAX;                      // min-walk sentinel
    #pragma unroll
    for (int k = 0; k < 8; k++) my[1+k] = v[k];
    my[9] = -FLT_MAX;                     // max-walk sentinel (c=8 case)
    __syncwarp();

    // Phase A: warp-local head/tail merges (shfl chains — proven fast in R12).
    {
        int mp = 1, np = c;
        float hv = my[1];
        float lv = my[np];
        #pragma unroll 1
        for (int r = 0; r < R; r++) {
            float bv = hv;
            #pragma unroll
            for (int off = 16; off; off >>= 1)
                bv = fmaxf(bv, __shfl_xor_sync(FULL, bv, off));
            unsigned m = __ballot_sync(FULL, hv == bv);
            if (lane == __ffs(m) - 1) { mp++; hv = my[mp]; }
            if (lane == 0) wt[wid][r] = bv;

            float sv = lv;
            #pragma unroll
            for (int off = 16; off; off >>= 1)
                sv = fminf(sv, __shfl_xor_sync(FULL, sv, off));
            unsigned m2 = __ballot_sync(FULL, lv == sv);
            if (lane == __ffs(m2) - 1) { np--; lv = my[np]; }
            if (lane == 0) wb[wid][r] = sv;
        }
        if (lane == 0) { wt[wid][20] = -FLT_MAX; wb[wid][20] = FLT_MAX; }
    }
    __syncthreads();

    // Phase B: two warps merge the 32 warp lists; bias added here.
    const float bias = cb[j];
    float* outT = g_mmh + ((bj*2 + half)*2 + 0)*20;
    float* outB = g_mmh + ((bj*2 + half)*2 + 1)*20;

    if (wid == 0) {          // top-20, descending
        int p = 0; float hv = wt[lane][0];
        #pragma unroll 1
        for (int r = 0; r < R; r++) {
            float bv = hv;
            #pragma unroll
            for (int off = 16; off; off >>= 1)
                bv = fmaxf(bv, __shfl_xor_sync(FULL, bv, off));
            unsigned m = __ballot_sync(FULL, hv == bv);
            if (lane == __ffs(m) - 1) { p++; hv = wt[lane][p]; }
            if (lane == 0) outT[r] = bv + bias;
        }
        if (lane == 0) __threadfence();   // writer publishes before the counter
    } else if (wid == 1) {   // bottom-20, ascending
        int p = 0; float lv = wb[lane][0];
        #pragma unroll 1
        for (int r = 0; r < R; r++) {
            float sv = lv;
            #pragma unroll
            for (int off = 16; off; off >>= 1)
                sv = fminf(sv, __shfl_xor_sync(FULL, sv, off));
            unsigned m = __ballot_sync(FULL, lv == sv);
            if (lane == __ffs(m) - 1) { p++; lv = wb[lane][p]; }
            if (lane == 0) outB[r] = sv + bias;
        }
        if (lane == 0) __threadfence();   // writer publishes before the counter
    }
    __syncthreads();

    // --- completion counter: last block runs the MLP ---
    if (tid == 0) {
        unsigned old = atomicAdd(&g_done, 1u);
        is_last = (old == NSEL - 1);
        if (is_last) g_done = 0;          // reset for next graph replay
    }
    __syncthreads();
    if (!is_last) return;

    // --- MLP phase (one block, 8 batch-groups of 128 threads) ---
    float* ml   = (float*)sbuf;                 // [8][800]  25600B
    float* sinp = (float*)(sbuf + 25600);       // [8][400]  12800B
    float* sh1  = (float*)(sbuf + 38400);       // [8][200]   6400B
    float* sh2  = (float*)(sbuf + 44800);       // [8][100]   3200B

    for (int i = tid; i < B*800; i += TPB2) ml[i] = __ldcg(&g_mmh[i]);
    __syncthreads();

    const int g  = tid >> 7;        // batch 0..7
    const int lt = tid & 127;
    float* mlg = ml + g*800;
    float* sg  = sinp + g*400;
    float* h1g = sh1 + g*H1;
    float* h2g = sh2 + g*H2;

    // Merge halves' sorted lists (threads lt<20 per group).
    if (lt < 2*J) {
        int jj = lt % J, bot = lt / J;
        const float* A  = mlg + jj*80 +      bot*20;
        const float* Bp = mlg + jj*80 + 40 + bot*20;
        int pa = 0, pb = 0;
        if (bot == 0) {
            #pragma unroll 1
            for (int r = 0; r < R; r++) {
                float av = (pa < 20) ? A[pa] : -FLT_MAX;
                float bv = (pb < 20) ? Bp[pb] : -FLT_MAX;
                if (av >= bv) { sg[jj*40 + r] = av; pa++; }
                else          { sg[jj*40 + r] = bv; pb++; }
            }
        } else {
            #pragma unroll 1
            for (int r = 0; r < R; r++) {
                float av = (pa < 20) ? A[pa] : FLT_MAX;
                float bv = (pb < 20) ? Bp[pb] : FLT_MAX;
                if (av <= bv) { sg[jj*40 + 39 - r] = av; pa++; }
                else          { sg[jj*40 + 39 - r] = bv; pb++; }
            }
        }
    }
    __syncthreads();

    // Layer 1: 400 -> 200. 50 threads/group, 4 outputs each (float4 weights).
    if (lt < H1/4) {
        int k0 = lt*4;
        float4 s4 = *(const float4*)&b1[k0];
        #pragma unroll 4
        for (int i = 0; i < 2*R*J; i++) {
            float xi = sg[i];
            float4 w4 = *(const float4*)&w1[i*H1 + k0];
            s4.x += xi*w4.x; s4.y += xi*w4.y; s4.z += xi*w4.z; s4.w += xi*w4.w;
        }
        h1g[k0+0] = 1.f/(1.f+expf(-s4.x));
        h1g[k0+1] = 1.f/(1.f+expf(-s4.y));
        h1g[k0+2] = 1.f/(1.f+expf(-s4.z));
        h1g[k0+3] = 1.f/(1.f+expf(-s4.w));
    }
    __syncthreads();

    // Layer 2: 200 -> 100. 25 threads/group, 4 outputs each.
    if (lt < H2/4) {
        int k0 = lt*4;
        float4 s4 = *(const float4*)&b2[k0];
        #pragma unroll 4
        for (int i = 0; i < H1; i++) {
            float xi = h1g[i];
            float4 w4 = *(const float4*)&w2[i*H2 + k0];
            s4.x += xi*w4.x; s4.y += xi*w4.y; s4.z += xi*w4.z; s4.w += xi*w4.w;
        }
        h2g[k0+0] = 1.f/(1.f+expf(-s4.x));
        h2g[k0+1] = 1.f/(1.f+expf(-s4.y));
        h2g[k0+2] = 1.f/(1.f+expf(-s4.z));
        h2g[k0+3] = 1.f/(1.f+expf(-s4.w));
    }
    __syncthreads();

    // Layer 3: 100 -> 2. 2 threads/group.
    if (lt < 2) {
        float sum = b3[lt];
        #pragma unroll 4
        for (int i = 0; i < H2; i++) sum += h2g[i] * w3[i*2 + lt];
        out[g*2 + lt] = sum;
    }
}

// ---------------------------------------------------------------------------
extern "C" void kernel_launch(void* const* d_in, const int* in_sizes, int n_in,
                              void* d_out, int out_size)
{
    const float* x  = (const float*)d_in[0];
    const float* cw = (const float*)d_in[1];
    const float* cb = (const float*)d_in[2];
    const float* w1 = (const float*)d_in[3];
    const float* b1 = (const float*)d_in[4];
    const float* w2 = (const float*)d_in[5];
    const float* b2 = (const float*)d_in[6];
    const float* w3 = (const float*)d_in[7];
    const float* b3 = (const float*)d_in[8];
    float* out = (float*)d_out;

    static int smem_set = 0;
    if (!smem_set) {
        cudaFuncSetAttribute(conv_kernel, cudaFuncAttributeMaxDynamicSharedMemorySize, SMEM_CONV);
        cudaFuncSetAttribute(select_kernel, cudaFuncAttributeMaxDynamicSharedMemorySize, SMEM_SEL);
        smem_set = 1;
    }

    dim3 g1(NBLK1, FS, B);
    conv_kernel<<<g1, TPB1, SMEM_CONV>>>(x, cw);
    select_kernel<<<NSEL, TPB2, SMEM_SEL>>>(cb, w1, b1, w2, b2, w3, b3, out);
}

// round 16
// speedup vs baseline: 1.3123x; 1.3123x over previous
#include <cuda_runtime.h>
#include <cuda_fp16.h>
#include <math.h>
#include <float.h>

#define B   8
#define F   2048
#define NN  10000
#define J   10
#define R   20
#define H1  200
#define H2  100

#define FS   16           // F splits
#define FC   (F/FS)       // 128 f-rows per block
#define TPB1 128
#define WINF 512          // floats per n-window (2KB transfers — do not shrink; R10)
#define NBLK1 ((NN + WINF - 1)/WINF)   // 20
#define NST  4            // pipeline stages
#define CROWS 2           // f-rows per stage/chunk (4KB stages)
#define NCHUNK (FC/CROWS) // 64

#define WS_BYTES    (FC*J*8)          // float2 dup weights: 10240
#define STAGE_BYTES (CROWS*WINF*4)    // 4096 per stage
#define SMEM_CONV   (WS_BYTES + NST*STAGE_BYTES + 64)   // ~26.7KB -> 6 CTAs/SM
// conv grid = 20*16*8 = 2560 over 148*6=888 capacity = 2.88 waves (96% avg residency)

// Scratch (device globals: no allocation allowed)
__device__ __align__(16) __half g_parth[(size_t)FS*B*J*NN];  // 25.6 MB fp16 partials
__device__ float g_mmh[B*J*2*2*20];   // per-(bj,half): top20 desc, bot20 asc

#define FMA2(acc, w, xv) asm("fma.rn.f32x2 %0, %1, %2, %0;" : "+l"(acc) : "l"(w), "l"(xv))

__device__ __forceinline__ unsigned smem_u32(const void* p) {
    return (unsigned)__cvta_generic_to_shared(p);
}
__device__ __forceinline__ void mbar_init(unsigned mbar, unsigned cnt) {
    asm volatile("mbarrier.init.shared::cta.b64 [%0], %1;" :: "r"(mbar), "r"(cnt) : "memory");
}
__device__ __forceinline__ void mbar_expect_tx(unsigned mbar, unsigned bytes) {
    asm volatile("mbarrier.arrive.expect_tx.shared::cta.b64 _, [%0], %1;" :: "r"(mbar), "r"(bytes) : "memory");
}
__device__ __forceinline__ void mbar_wait(unsigned mbar, unsigned phase) {
    asm volatile(
        "{\n\t.reg .pred P;\n\t"
        "W_%=:\n\t"
        "mbarrier.try_wait.parity.shared::cta.b64 P, [%0], %1, 0x989680;\n\t"
        "@!P bra W_%=;\n\t}"
        :: "r"(mbar), "r"(phase) : "memory");
}
__device__ __forceinline__ void bulk_g2s(unsigned dst, const void* src, unsigned bytes, unsigned mbar) {
    asm volatile(
        "cp.async.bulk.shared::cta.global.mbarrier::complete_tx::bytes [%0], [%1], %2, [%3];"
        :: "r"(dst), "l"(src), "r"(bytes), "r"(mbar) : "memory");
}

// ---------------------------------------------------------------------------
// Kernel 1: 1x1 conv partials via cp.async.bulk staging (unchanged R12 WIN).
// g_parth[fs][b][j][n] = (half) sum_{f in chunk} x[b,f,n]*w[j,f]
// ---------------------------------------------------------------------------
__global__ __launch_bounds__(TPB1, 6)
void conv_kernel(const float* __restrict__ x, const float* __restrict__ cw)
{
    extern __shared__ __align__(16) unsigned char smem_raw[];
    float2* ws     = (float2*)smem_raw;                          // [FC][J] dup pairs
    float*  stages = (float*)(smem_raw + WS_BYTES);              // [NST][CROWS][WINF]
    unsigned mbar0 = smem_u32(smem_raw + WS_BYTES + NST*STAGE_BYTES);

    const int b   = blockIdx.z;
    const int fs  = blockIdx.y;
    const int f0  = fs * FC;
    const int n0  = blockIdx.x * WINF;
    const int wfl = (NN - n0 < WINF) ? (NN - n0) : WINF;
    const unsigned wbytes = (unsigned)wfl * 4u;
    const int tid = threadIdx.x;

    for (int i = tid; i < FC*J; i += TPB1) {
        int f = i / J, j = i - f*J;
        float w = cw[j*F + f0 + f];
        ws[i] = make_float2(w, w);
    }
    if (tid == 0) {
        #pragma unroll
        for (int s = 0; s < NST; s++) mbar_init(mbar0 + 8*s, 1);
    }
    __syncthreads();

    const float* xbase = x + ((size_t)b*F + f0)*NN + n0;

    if (tid == 0) {
        #pragma unroll
        for (int s = 0; s < NST; s++) {
            mbar_expect_tx(mbar0 + 8*s, wbytes * CROWS);
            unsigned dst = smem_u32(stages + s*CROWS*WINF);
            const float* src = xbase + (size_t)(s*CROWS)*NN;
            #pragma unroll
            for (int u = 0; u < CROWS; u++)
                bulk_g2s(dst + u*WINF*4, src + (size_t)u*NN, wbytes, mbar0 + 8*s);
        }
    }

    unsigned long long acc0[J], acc1[J];
    #pragma unroll
    for (int j = 0; j < J; j++) { acc0[j] = 0ull; acc1[j] = 0ull; }

    const int col = 4*tid;

    #pragma unroll 1
    for (int c = 0; c < NCHUNK; c++) {
        const int slot = c & (NST-1);
        mbar_wait(mbar0 + 8*slot, (c >> 2) & 1);

        const float* st = stages + slot*CROWS*WINF + col;
        #pragma unroll
        for (int u = 0; u < CROWS; u++) {
            ulonglong2 xv = *(const ulonglong2*)(st + u*WINF);
            const ulonglong2* wp = (const ulonglong2*)&ws[(c*CROWS + u)*J];
            #pragma unroll
            for (int jj = 0; jj < 5; jj++) {
                ulonglong2 w2 = wp[jj];
                FMA2(acc0[2*jj  ], w2.x, xv.x);
                FMA2(acc1[2*jj  ], w2.x, xv.y);
                FMA2(acc0[2*jj+1], w2.y, xv.x);
                FMA2(acc1[2*jj+1], w2.y, xv.y);
            }
        }
        __syncthreads();
        if (tid == 0 && c + NST < NCHUNK) {
            int nc = c + NST;
            mbar_expect_tx(mbar0 + 8*slot, wbytes * CROWS);
            unsigned dst = smem_u32(stages + slot*CROWS*WINF);
            const float* src = xbase + (size_t)(nc*CROWS)*NN;
            #pragma unroll
            for (int u = 0; u < CROWS; u++)
                bulk_g2s(dst + u*WINF*4, src + (size_t)u*NN, wbytes, mbar0 + 8*slot);
        }
    }

    if (col < wfl) {
        __half* outp = g_parth + (((size_t)fs*B + b)*J)*NN + n0 + col;
        #pragma unroll
        for (int j = 0; j < J; j++) {
            float a, bb, cc, d;
            asm("mov.b64 {%0,%1}, %2;" : "=f"(a), "=f"(bb) : "l"(acc0[j]));
            asm("mov.b64 {%0,%1}, %2;" : "=f"(cc), "=f"(d) : "l"(acc1[j]));
            __half2 h0 = __floats2half2_rn(a, bb);
            __half2 h1 = __floats2half2_rn(cc, d);
            uint2 u2;
            u2.x = reinterpret_cast<unsigned&>(h0);
            u2.y = reinterpret_cast<unsigned&>(h1);
            *(uint2*)(outp + (size_t)j*NN) = u2;
        }
    }
}

// ---------------------------------------------------------------------------
// Kernel 2: per-(b,j,half) top-20 / bottom-20. uint4 (16B) partial loads:
// halves the LDG count vs uint2 — select was LSU-issue bound (R14 finding).
// 640 threads; 625 active cover the half-row (one uint4 of 8 halves per fs).
// ---------------------------------------------------------------------------
#define TPB2 640
#define QTOT (NN/8)           // 1250 uint4 per row
#define HQ   (QTOT/2)         // 625 per half
#define LSTRIDE 10            // sentinel + 8 vals + tail sentinel
#define NW2  (TPB2/32)        // 20 warps

__global__ __launch_bounds__(TPB2)
void select_kernel(const float* __restrict__ cb,
                   const float* __restrict__ w1, const float* __restrict__ w2,
                   const float* __restrict__ w3)
{
    __shared__ float s[TPB2*LSTRIDE];       // 25.6KB per-thread sorted lists
    __shared__ float wt[NW2][21], wb[NW2][21];

    const int bid = blockIdx.x;
    const int half = bid & 1, bj = bid >> 1;
    const int b = bj / J, j = bj - b*J;
    const int tid = threadIdx.x;
    const int lane = tid & 31, wid = tid >> 5;
    const unsigned FULL = 0xffffffffu;

    // Warm L2 with the MLP weights.
    {
        int gid = bid * TPB2 + tid;
        if (gid < (2*R*J)*H1/32) {
            asm volatile("prefetch.global.L2 [%0];" :: "l"(w1 + gid*32));
        } else if (gid < (2*R*J)*H1/32 + H1*H2/32) {
            asm volatile("prefetch.global.L2 [%0];" :: "l"(w2 + (gid - (2*R*J)*H1/32)*32));
        } else if (gid < (2*R*J)*H1/32 + H1*H2/32 + 7) {
            asm volatile("prefetch.global.L2 [%0];" :: "l"(w3 + (gid - (2*R*J)*H1/32 - H1*H2/32)*32));
        }
    }

    float v[8];
    #pragma unroll
    for (int k = 0; k < 8; k++) v[k] = -FLT_MAX;
    int c = 0;
    if (tid < HQ) {
        int q = half*HQ + tid;               // uint4 index within row
        float a0=0.f,a1=0.f,a2=0.f,a3=0.f,a4=0.f,a5=0.f,a6=0.f,a7=0.f;
        #pragma unroll
        for (int fs = 0; fs < FS; fs++) {
            const uint4* p = (const uint4*)(g_parth + (((size_t)fs*B + b)*J + j)*NN);
            uint4 raw = p[q];                 // 8 halves, one LDG.128
            __half2 h0 = reinterpret_cast<__half2&>(raw.x);
            __half2 h1 = reinterpret_cast<__half2&>(raw.y);
            __half2 h2 = reinterpret_cast<__half2&>(raw.z);
            __half2 h3 = reinterpret_cast<__half2&>(raw.w);
            float2 f0 = __half22float2(h0), f1 = __half22float2(h1);
            float2 f2 = __half22float2(h2), f3 = __half22float2(h3);
            a0 += f0.x; a1 += f0.y; a2 += f1.x; a3 += f1.y;
            a4 += f2.x; a5 += f2.y; a6 += f3.x; a7 += f3.y;
        }
        v[0]=a0; v[1]=a1; v[2]=a2; v[3]=a3; v[4]=a4; v[5]=a5; v[6]=a6; v[7]=a7;
        c = 8;
    }

    // Odd-even transposition sort, descending (8 passes).
    #pragma unroll
    for (int pass = 0; pass < 8; pass++) {
        #pragma unroll
        for (int i = (pass & 1); i + 1 < 8; i += 2) {
            float hi = fmaxf(v[i], v[i+1]);
            float lo = fminf(v[i], v[i+1]);
            v[i] = hi; v[i+1] = lo;
        }
    }

    float* my = s + tid*LSTRIDE;
    my[0] = FLT_MAX;                      // min-walk sentinel
    #pragma unroll
    for (int k = 0; k < 8; k++) my[1+k] = v[k];
    my[9] = -FLT_MAX;                     // max-walk sentinel
    __syncwarp();

    // Phase A: warp-local head/tail merges (shfl chains). Index clamps guard
    // lanes that hold only pads (tid >= HQ).
    {
        int mp = 1, np = c;               // c==0 -> my[0]=+inf, never wins min
        float hv = my[1];
        float lv = my[np];
        #pragma unroll 1
        for (int r = 0; r < R; r++) {
            float bv = hv;
            #pragma unroll
            for (int off = 16; off; off >>= 1)
                bv = fmaxf(bv, __shfl_xor_sync(FULL, bv, off));
            unsigned m = __ballot_sync(FULL, hv == bv);
            if (lane == __ffs(m) - 1) { mp++; if (mp > 9) mp = 9; hv = my[mp]; }
            if (lane == 0) wt[wid][r] = bv;

            float sv = lv;
            #pragma unroll
            for (int off = 16; off; off >>= 1)
                sv = fminf(sv, __shfl_xor_sync(FULL, sv, off));
            unsigned m2 = __ballot_sync(FULL, lv == sv);
            if (lane == __ffs(m2) - 1) { np--; if (np < 0) np = 0; lv = my[np]; }
            if (lane == 0) wb[wid][r] = sv;
        }
        if (lane == 0) { wt[wid][20] = -FLT_MAX; wb[wid][20] = FLT_MAX; }
    }
    __syncthreads();

    // Phase B: two warps merge the NW2 warp lists; bias added here.
    const float bias = cb[j];
    float* outT = g_mmh + ((bj*2 + half)*2 + 0)*20;
    float* outB = g_mmh + ((bj*2 + half)*2 + 1)*20;

    if (wid == 0) {          // top-20, descending
        int p = 0;
        float hv = (lane < NW2) ? wt[lane][0] : -FLT_MAX;
        #pragma unroll 1
        for (int r = 0; r < R; r++) {
            float bv = hv;
            #pragma unroll
            for (int off = 16; off; off >>= 1)
                bv = fmaxf(bv, __shfl_xor_sync(FULL, bv, off));
            unsigned m = __ballot_sync(FULL, hv == bv);
            if (lane == __ffs(m) - 1) { p++; hv = wt[lane][p]; }   // winner < NW2
            if (lane == 0) outT[r] = bv + bias;
        }
    } else if (wid == 1) {   // bottom-20, ascending
        int p = 0;
        float lv = (lane < NW2) ? wb[lane][0] : FLT_MAX;
        #pragma unroll 1
        for (int r = 0; r < R; r++) {
            float sv = lv;
            #pragma unroll
            for (int off = 16; off; off >>= 1)
                sv = fminf(sv, __shfl_xor_sync(FULL, sv, off));
            unsigned m = __ballot_sync(FULL, lv == sv);
            if (lane == __ffs(m) - 1) { p++; lv = wb[lane][p]; }
            if (lane == 0) outB[r] = sv + bias;
        }
    }
}

// ---------------------------------------------------------------------------
// Kernel 3: merge halves (from smem) + MLP 400->200->100->2 (R12 proven).
// ---------------------------------------------------------------------------
__global__ __launch_bounds__(512)
void mlp_kernel(const float* __restrict__ w1, const float* __restrict__ b1,
                const float* __restrict__ w2, const float* __restrict__ b2,
                const float* __restrict__ w3, const float* __restrict__ b3,
                float* __restrict__ out)
{
    __shared__ float lists[800];    // this b's g_mmh span (coalesced load)
    __shared__ float sin_[2*R*J];   // [J][40]: top desc then bottom desc
    __shared__ float part1[2][H1];
    __shared__ float sh1[H1];
    __shared__ float part2[2][H2];
    __shared__ float sh2[H2];
    const int b = blockIdx.x;
    const int tid = threadIdx.x;

    for (int i = tid; i < 800; i += 512) lists[i] = g_mmh[b*800 + i];
    __syncthreads();

    // Merge the two halves' sorted lists (threads 0..19), all from smem.
    if (tid < 2*J) {
        int j = tid % J, bot = tid / J;
        const float* A  = lists + j*80 +      bot*20;   // half 0
        const float* Bp = lists + j*80 + 40 + bot*20;   // half 1
        int pa = 0, pb = 0;
        if (bot == 0) {          // descending merge, take 20 largest
            #pragma unroll 1
            for (int r = 0; r < R; r++) {
                float av = (pa < 20) ? A[pa] : -FLT_MAX;
                float bv = (pb < 20) ? Bp[pb] : -FLT_MAX;
                if (av >= bv) { sin_[j*40 + r] = av; pa++; }
                else          { sin_[j*40 + r] = bv; pb++; }
            }
        } else {                 // ascending merge, take 20 smallest -> slot 39-r
            #pragma unroll 1
            for (int r = 0; r < R; r++) {
                float av = (pa < 20) ? A[pa] : FLT_MAX;
                float bv = (pb < 20) ? Bp[pb] : FLT_MAX;
                if (av <= bv) { sin_[j*40 + 39 - r] = av; pa++; }
                else          { sin_[j*40 + 39 - r] = bv; pb++; }
            }
        }
    }
    __syncthreads();

    // Layer 1: 400->200, i-range split across 2 threads per output.
    if (tid < 2*H1) {
        int k = tid % H1, part = tid / H1;
        float s = (part == 0) ? b1[k] : 0.f;
        int i0 = part * (2*R*J/2);
        #pragma unroll 16
        for (int i = 0; i < 2*R*J/2; i++) s += sin_[i0 + i] * w1[(i0 + i)*H1 + k];
        part1[part][k] = s;
    }
    __syncthreads();
    if (tid < H1) sh1[tid] = 1.f / (1.f + expf(-(part1[0][tid] + part1[1][tid])));
    __syncthreads();

    // Layer 2: 200->100, i-range split across 2 threads per output.
    if (tid < 2*H2) {
        int k = tid % H2, part = tid / H2;
        float s = (part == 0) ? b2[k] : 0.f;
        int i0 = part * (H1/2);
        #pragma unroll 16
        for (int i = 0; i < H1/2; i++) s += sh1[i0 + i] * w2[(i0 + i)*H2 + k];
        part2[part][k] = s;
    }
    __syncthreads();
    if (tid < H2) sh2[tid] = 1.f / (1.f + expf(-(part2[0][tid] + part2[1][tid])));
    __syncthreads();

    // Layer 3: 100->2 via two warp reductions.
    if (tid < 64) {
        int k = tid >> 5, lane = tid & 31;
        float s = 0.f;
        #pragma unroll
        for (int i = lane; i < H2; i += 32) s += sh2[i] * w3[i*2 + k];
        #pragma unroll
        for (int off = 16; off; off >>= 1) s += __shfl_down_sync(0xffffffffu, s, off);
        if (lane == 0) out[b*2 + k] = s + b3[k];
    }
}

// ---------------------------------------------------------------------------
extern "C" void kernel_launch(void* const* d_in, const int* in_sizes, int n_in,
                              void* d_out, int out_size)
{
    const float* x  = (const float*)d_in[0];
    const float* cw = (const float*)d_in[1];
    const float* cb = (const float*)d_in[2];
    const float* w1 = (const float*)d_in[3];
    const float* b1 = (const float*)d_in[4];
    const float* w2 = (const float*)d_in[5];
    const float* b2 = (const float*)d_in[6];
    const float* w3 = (const float*)d_in[7];
    const float* b3 = (const float*)d_in[8];
    float* out = (float*)d_out;

    static int smem_set = 0;
    if (!smem_set) {
        cudaFuncSetAttribute(conv_kernel, cudaFuncAttributeMaxDynamicSharedMemorySize, SMEM_CONV);
        smem_set = 1;
    }

    dim3 g1(NBLK1, FS, B);
    conv_kernel<<<g1, TPB1, SMEM_CONV>>>(x, cw);
    select_kernel<<<B*J*2, TPB2>>>(cb, w1, w2, w3);
    mlp_kernel<<<B, 512>>>(w1, b1, w2, b2, w3, b3, out);
}